// round 7
// baseline (speedup 1.0000x reference)
#include <cuda_runtime.h>
#include <math.h>

#define BB  16
#define CC  64
#define HH  128
#define WW  128
#define HW  (HH*WW)
#define BC  (BB*CC)

// Per-(b,c) x-space threshold T = logit(sigmoid(max x) - 0.01), from k1.
__device__ float g_T[BC];

__device__ __forceinline__ float sigmoidf_(float v) {
    return 1.0f / (1.0f + expf(-v));
}

// ---------------------------------------------------------------------------
// K1: per-(b,c) plane. max(x) -> ps, threshold T; masked sums -> bbox row.
// (unchanged from round 5/6)
// ---------------------------------------------------------------------------
__global__ __launch_bounds__(256) void k1_stats(
    const float* __restrict__ x,
    const float* __restrict__ w_bbx,
    const float* __restrict__ w_width,
    const float* __restrict__ w_width_sh,
    const float* __restrict__ w_height,
    const float* __restrict__ w_height_sh,
    float* __restrict__ out)
{
    const int bc = blockIdx.x;
    const int b  = bc / CC;
    const int c  = bc % CC;
    const float* __restrict__ xp = x + (size_t)bc * HW;
    const int t = threadIdx.x;

    float mx = -INFINITY;
    #pragma unroll
    for (int j = 0; j < 16; ++j) {
        float4 v = *(const float4*)(xp + 1024 * j + 4 * t);
        mx = fmaxf(fmaxf(fmaxf(mx, v.x), fmaxf(v.y, v.z)), v.w);
    }
    __shared__ float red[8];
    #pragma unroll
    for (int o = 16; o; o >>= 1) mx = fmaxf(mx, __shfl_xor_sync(0xffffffffu, mx, o));
    if ((t & 31) == 0) red[t >> 5] = mx;
    __syncthreads();
    __shared__ float sT, sps;
    if (t == 0) {
        float v = red[0];
        #pragma unroll
        for (int k = 1; k < 8; ++k) v = fmaxf(v, red[k]);
        float ps = sigmoidf_(v);
        float M  = ps - 0.01f;
        float T;
        if (M > 0.0f) {
            double dM = (double)M;
            T = (float)log(dM / (1.0 - dM));
        } else {
            T = -INFINITY;
        }
        sT = T; sps = ps;
        g_T[bc] = T;
    }
    __syncthreads();
    const float T = sT;

    float cw[11], ch[11];
    #pragma unroll
    for (int k = 0; k < 11; ++k) { cw[k] = w_width[c*11+k]; ch[k] = w_height[c*11+k]; }
    const float s0 = w_bbx[c] * 128.0f;
    const float sW = s0 * w_width_sh[c];
    const float sH = s0 * w_height_sh[c];

    float S = 0.f, Sc = 0.f, Sr = 0.f, Sw = 0.f, Sh = 0.f;
    #pragma unroll
    for (int j = 0; j < 16; ++j) {
        const int i0 = 1024 * j + 4 * t;
        float4 v4 = *(const float4*)(xp + i0);
        float vv[4] = {v4.x, v4.y, v4.z, v4.w};
        if (vv[0] > T || vv[1] > T || vv[2] > T || vv[3] > T) {
            #pragma unroll
            for (int u = 0; u < 4; ++u) {
                float v = vv[u];
                if (v > T) {
                    int i = i0 + u;
                    int row = i >> 7, col = i & 127;
                    S  += v;
                    Sc += (float)col * v;
                    Sr += (float)row * v;
                    float wvv = 0.f;
                    #pragma unroll
                    for (int k = 0; k < 11; ++k) {
                        int cc2 = col - 5 + k;
                        if (cc2 >= 0 && cc2 < WW) wvv = fmaf(xp[(row << 7) + cc2], cw[k], wvv);
                    }
                    float hvv = 0.f;
                    #pragma unroll
                    for (int k = 0; k < 11; ++k) {
                        int rr = row - 5 + k;
                        if (rr >= 0 && rr < HH) hvv = fmaf(xp[(rr << 7) + col], ch[k], hvv);
                    }
                    Sw += wvv * sW * v;
                    Sh += hvv * sH * v;
                }
            }
        }
    }
    __shared__ float racc[5][8];
    #pragma unroll
    for (int o = 16; o; o >>= 1) {
        S  += __shfl_xor_sync(0xffffffffu, S,  o);
        Sc += __shfl_xor_sync(0xffffffffu, Sc, o);
        Sr += __shfl_xor_sync(0xffffffffu, Sr, o);
        Sw += __shfl_xor_sync(0xffffffffu, Sw, o);
        Sh += __shfl_xor_sync(0xffffffffu, Sh, o);
    }
    if ((t & 31) == 0) {
        int w5 = t >> 5;
        racc[0][w5] = S; racc[1][w5] = Sc; racc[2][w5] = Sr; racc[3][w5] = Sw; racc[4][w5] = Sh;
    }
    __syncthreads();
    if (t == 0) {
        float a0=0,a1=0,a2=0,a3=0,a4=0;
        #pragma unroll
        for (int k = 0; k < 8; ++k) { a0+=racc[0][k]; a1+=racc[1][k]; a2+=racc[2][k]; a3+=racc[3][k]; a4+=racc[4][k]; }
        float ws = a3 / a0, hs = a4 / a0;
        float x1 = a1 / a0 - ws * 0.5f;
        float y1 = a2 / a0 - hs * 0.5f;
        float* bb = out + (size_t)BB * 3 * CC * HW + (size_t)bc * 6;
        bb[0] = (float)b; bb[1] = x1; bb[2] = y1;
        bb[3] = x1 + ws;  bb[4] = y1 + hs; bb[5] = sps;
    }
}

// ---------------------------------------------------------------------------
// kS: score branch. Pure streaming argmax over channels; no smem tile.
// grid (16, BB) x 256 threads, 4 pixels each.
// ---------------------------------------------------------------------------
__global__ __launch_bounds__(256) void kS_score(
    const float* __restrict__ x, float* __restrict__ out)
{
    const int t = threadIdx.x;
    const int b = blockIdx.y;
    const int px = (blockIdx.x * 256 + t) << 2;

    __shared__ float sT[CC];
    if (t < CC) sT[t] = g_T[b * CC + t];
    __syncthreads();

    const float* xp = x + (size_t)(b * CC) * HW + px;
    float mv[4] = {-INFINITY, -INFINITY, -INFINITY, -INFINITY};
    int   mi[4] = {0, 0, 0, 0};

    #pragma unroll 8
    for (int c = 0; c < CC; ++c) {
        float4 v = __ldg((const float4*)(xp + (size_t)c * HW));
        const float Tc = sT[c];
        float s0 = (v.x > Tc) ? v.x : 0.f;
        float s1 = (v.y > Tc) ? v.y : 0.f;
        float s2 = (v.z > Tc) ? v.z : 0.f;
        float s3 = (v.w > Tc) ? v.w : 0.f;
        if (s0 > mv[0]) { mv[0] = s0; mi[0] = c; }
        if (s1 > mv[1]) { mv[1] = s1; mi[1] = c; }
        if (s2 > mv[2]) { mv[2] = s2; mi[2] = c; }
        if (s3 > mv[3]) { mv[3] = s3; mi[3] = c; }
    }

    float* o = out + (size_t)(b * 3 * CC) * HW + px;
    #pragma unroll 8
    for (int c = 0; c < CC; ++c) {
        __stcs((float4*)(o + (size_t)c * HW),
               make_float4(mi[0]==c ? mv[0] : 0.f, mi[1]==c ? mv[1] : 0.f,
                           mi[2]==c ? mv[2] : 0.f, mi[3]==c ? mv[3] : 0.f));
    }
}

// ---------------------------------------------------------------------------
// kW: width branch. Horizontal conv only -> tile has NO vertical halo.
// 128 threads: r=t>>5 (4 rows), c4=(t&31)<<2. grid (32, BB).
// Double-buffered 4x144 tile, one barrier per channel.
// ---------------------------------------------------------------------------
#define WTP 144

__global__ __launch_bounds__(128) void kW_width(
    const float* __restrict__ x,
    const float* __restrict__ w_bbx,
    const float* __restrict__ w_width,
    const float* __restrict__ w_width_sh,
    float* __restrict__ out)
{
    __shared__ float tile[2][4 * WTP];
    __shared__ float scw[CC * 11];
    __shared__ float ssW[CC];

    const int t    = threadIdx.x;        // 0..127
    const int b    = blockIdx.y;
    const int row0 = blockIdx.x * 4;     // grid.x = 32
    const int r    = t >> 5;             // 0..3
    const int c4   = (t & 31) << 2;      // 0..124

    // zero pads once (fills never touch them)
    for (int i = t; i < 4 * WTP; i += 128) {
        int col = i % WTP;
        if (col < 8 || col >= 136) { tile[0][i] = 0.f; tile[1][i] = 0.f; }
    }
    for (int i = t; i < CC * 11; i += 128) scw[i] = w_width[i];
    if (t < CC) ssW[t] = w_bbx[t] * 128.0f * w_width_sh[t];

    const int fjr  = t >> 7;             // unused (kept simple below)
    const float* xp0 = x + (size_t)(b * CC) * HW + (row0 << 7);

    // fill staging: 4 elements/thread cover 4x128 (rows all in-image)
    float regs[4];
    {
        #pragma unroll
        for (int j = 0; j < 4; ++j)
            regs[j] = __ldg(xp0 + t + j * 128);
        #pragma unroll
        for (int j = 0; j < 4; ++j) {
            int idx = t + j * 128;
            tile[0][(idx >> 7) * WTP + 8 + (idx & 127)] = regs[j];
        }
    }

    float mW[4] = {-INFINITY, -INFINITY, -INFINITY, -INFINITY};
    int   iW[4] = {0, 0, 0, 0};

    for (int c = 0; c < CC; ++c) {
        const int cur = c & 1;
        if (c + 1 < CC) {
            const float* xp = xp0 + (size_t)(c + 1) * HW;
            #pragma unroll
            for (int j = 0; j < 4; ++j)
                regs[j] = __ldg(xp + t + j * 128);
        }
        __syncthreads();

        const float* tl = tile[cur];
        float in[20];
        {
            const float* hrow = &tl[r * WTP + c4];   // data col c4-8
            #pragma unroll
            for (int m = 0; m < 5; ++m) {
                float4 v = *(const float4*)(hrow + 4 * m);
                in[4*m+0] = v.x; in[4*m+1] = v.y; in[4*m+2] = v.z; in[4*m+3] = v.w;
            }
        }
        float wv[4] = {0.f, 0.f, 0.f, 0.f};
        #pragma unroll
        for (int k = 0; k < 11; ++k) {
            float ck = scw[c * 11 + k];
            wv[0] = fmaf(in[3 + k], ck, wv[0]);
            wv[1] = fmaf(in[4 + k], ck, wv[1]);
            wv[2] = fmaf(in[5 + k], ck, wv[2]);
            wv[3] = fmaf(in[6 + k], ck, wv[3]);
        }
        const float sWc = ssW[c];
        #pragma unroll
        for (int j = 0; j < 4; ++j) {
            float w_ = wv[j] * sWc;
            if (w_ > mW[j]) { mW[j] = w_; iW[j] = c; }
        }

        if (c + 1 < CC) {
            float* tn = tile[cur ^ 1];
            #pragma unroll
            for (int j = 0; j < 4; ++j) {
                int idx = t + j * 128;
                tn[(idx >> 7) * WTP + 8 + (idx & 127)] = regs[j];
            }
        }
    }

    float* o = out + ((size_t)(b * 3 * CC) + CC) * HW + ((size_t)(row0 + r) << 7) + c4;
    #pragma unroll 8
    for (int c = 0; c < CC; ++c) {
        __stcs((float4*)(o + (size_t)c * HW),
               make_float4(iW[0]==c ? mW[0] : 0.f, iW[1]==c ? mW[1] : 0.f,
                           iW[2]==c ? mW[2] : 0.f, iW[3]==c ? mW[3] : 0.f));
    }
}

// ---------------------------------------------------------------------------
// kH: height branch. Vertical conv, column-per-thread, NO smem data tile,
// NO barriers in the channel loop. Each thread: 1 column x 8 output rows,
// reads its 18 halo rows straight from L2 (coalesced per warp).
// 128 threads (= 128 columns). grid (16, BB).
// ---------------------------------------------------------------------------
#define HRG 8

__global__ __launch_bounds__(128) void kH_height(
    const float* __restrict__ x,
    const float* __restrict__ w_bbx,
    const float* __restrict__ w_height,
    const float* __restrict__ w_height_sh,
    float* __restrict__ out)
{
    __shared__ float sch[CC * 11];
    __shared__ float ssH[CC];

    const int t    = threadIdx.x;        // column 0..127
    const int b    = blockIdx.y;
    const int row0 = blockIdx.x * HRG;   // grid.x = 16

    for (int i = t; i < CC * 11; i += 128) sch[i] = w_height[i];
    if (t < CC) ssH[t] = w_bbx[t] * 128.0f * w_height_sh[t];
    __syncthreads();

    float mH[HRG];
    int   iH[HRG];
    #pragma unroll
    for (int j = 0; j < HRG; ++j) { mH[j] = -INFINITY; iH[j] = 0; }

    const float* xp0 = x + (size_t)(b * CC) * HW + t;

    for (int c = 0; c < CC; ++c) {
        const float* xp = xp0 + (size_t)c * HW;
        const float* ck = &sch[c * 11];
        float acc[HRG];
        #pragma unroll
        for (int j = 0; j < HRG; ++j) acc[j] = 0.f;

        #pragma unroll
        for (int k = 0; k < HRG + 10; ++k) {     // 18 input rows
            int gr = row0 - 5 + k;
            float v = (gr >= 0 && gr < HH) ? __ldg(xp + (gr << 7)) : 0.f;
            #pragma unroll
            for (int j = 0; j < HRG; ++j) {
                if (k - j >= 0 && k - j < 11)
                    acc[j] = fmaf(v, ck[k - j], acc[j]);
            }
        }
        const float sHc = ssH[c];
        #pragma unroll
        for (int j = 0; j < HRG; ++j) {
            float h_ = acc[j] * sHc;
            if (h_ > mH[j]) { mH[j] = h_; iH[j] = c; }
        }
    }

    float* o = out + ((size_t)(b * 3 * CC) + 2 * CC) * HW + ((size_t)row0 << 7) + t;
    for (int c = 0; c < CC; ++c) {
        #pragma unroll
        for (int j = 0; j < HRG; ++j)
            __stcs(o + (size_t)c * HW + (j << 7), iH[j]==c ? mH[j] : 0.f);
    }
}

extern "C" void kernel_launch(void* const* d_in, const int* in_sizes, int n_in,
                              void* d_out, int out_size)
{
    const float* x           = (const float*)d_in[0];
    const float* w_bbx       = (const float*)d_in[1];
    const float* w_width     = (const float*)d_in[2];
    const float* w_width_sh  = (const float*)d_in[3];
    const float* w_height    = (const float*)d_in[4];
    const float* w_height_sh = (const float*)d_in[5];
    float* out = (float*)d_out;

    k1_stats<<<BC, 256>>>(x, w_bbx, w_width, w_width_sh, w_height, w_height_sh, out);

    dim3 gS(16, BB);
    kS_score<<<gS, 256>>>(x, out);

    dim3 gW(32, BB);
    kW_width<<<gW, 128>>>(x, w_bbx, w_width, w_width_sh, out);

    dim3 gH(16, BB);
    kH_height<<<gH, 128>>>(x, w_bbx, w_height, w_height_sh, out);
}

// round 8
// speedup vs baseline: 1.6841x; 1.6841x over previous
#include <cuda_runtime.h>
#include <math.h>

#define BB  16
#define CC  64
#define HH  128
#define WW  128
#define HW  (HH*WW)
#define BC  (BB*CC)

// Per-(b,c) x-space threshold T = logit(sigmoid(max x) - 0.01), from k1.
__device__ float g_T[BC];

__device__ __forceinline__ float sigmoidf_(float v) {
    return 1.0f / (1.0f + expf(-v));
}

// ---------------------------------------------------------------------------
// K1: per-(b,c) plane. max(x) -> ps, threshold T; masked sums -> bbox row.
// (unchanged — passing since round 3)
// ---------------------------------------------------------------------------
__global__ __launch_bounds__(256) void k1_stats(
    const float* __restrict__ x,
    const float* __restrict__ w_bbx,
    const float* __restrict__ w_width,
    const float* __restrict__ w_width_sh,
    const float* __restrict__ w_height,
    const float* __restrict__ w_height_sh,
    float* __restrict__ out)
{
    const int bc = blockIdx.x;
    const int b  = bc / CC;
    const int c  = bc % CC;
    const float* __restrict__ xp = x + (size_t)bc * HW;
    const int t = threadIdx.x;

    float mx = -INFINITY;
    #pragma unroll
    for (int j = 0; j < 16; ++j) {
        float4 v = *(const float4*)(xp + 1024 * j + 4 * t);
        mx = fmaxf(fmaxf(fmaxf(mx, v.x), fmaxf(v.y, v.z)), v.w);
    }
    __shared__ float red[8];
    #pragma unroll
    for (int o = 16; o; o >>= 1) mx = fmaxf(mx, __shfl_xor_sync(0xffffffffu, mx, o));
    if ((t & 31) == 0) red[t >> 5] = mx;
    __syncthreads();
    __shared__ float sT, sps;
    if (t == 0) {
        float v = red[0];
        #pragma unroll
        for (int k = 1; k < 8; ++k) v = fmaxf(v, red[k]);
        float ps = sigmoidf_(v);
        float M  = ps - 0.01f;
        float T;
        if (M > 0.0f) {
            double dM = (double)M;
            T = (float)log(dM / (1.0 - dM));
        } else {
            T = -INFINITY;
        }
        sT = T; sps = ps;
        g_T[bc] = T;
    }
    __syncthreads();
    const float T = sT;

    float cw[11], ch[11];
    #pragma unroll
    for (int k = 0; k < 11; ++k) { cw[k] = w_width[c*11+k]; ch[k] = w_height[c*11+k]; }
    const float s0 = w_bbx[c] * 128.0f;
    const float sW = s0 * w_width_sh[c];
    const float sH = s0 * w_height_sh[c];

    float S = 0.f, Sc = 0.f, Sr = 0.f, Sw = 0.f, Sh = 0.f;
    #pragma unroll
    for (int j = 0; j < 16; ++j) {
        const int i0 = 1024 * j + 4 * t;
        float4 v4 = *(const float4*)(xp + i0);
        float vv[4] = {v4.x, v4.y, v4.z, v4.w};
        if (vv[0] > T || vv[1] > T || vv[2] > T || vv[3] > T) {
            #pragma unroll
            for (int u = 0; u < 4; ++u) {
                float v = vv[u];
                if (v > T) {
                    int i = i0 + u;
                    int row = i >> 7, col = i & 127;
                    S  += v;
                    Sc += (float)col * v;
                    Sr += (float)row * v;
                    float wvv = 0.f;
                    #pragma unroll
                    for (int k = 0; k < 11; ++k) {
                        int cc2 = col - 5 + k;
                        if (cc2 >= 0 && cc2 < WW) wvv = fmaf(xp[(row << 7) + cc2], cw[k], wvv);
                    }
                    float hvv = 0.f;
                    #pragma unroll
                    for (int k = 0; k < 11; ++k) {
                        int rr = row - 5 + k;
                        if (rr >= 0 && rr < HH) hvv = fmaf(xp[(rr << 7) + col], ch[k], hvv);
                    }
                    Sw += wvv * sW * v;
                    Sh += hvv * sH * v;
                }
            }
        }
    }
    __shared__ float racc[5][8];
    #pragma unroll
    for (int o = 16; o; o >>= 1) {
        S  += __shfl_xor_sync(0xffffffffu, S,  o);
        Sc += __shfl_xor_sync(0xffffffffu, Sc, o);
        Sr += __shfl_xor_sync(0xffffffffu, Sr, o);
        Sw += __shfl_xor_sync(0xffffffffu, Sw, o);
        Sh += __shfl_xor_sync(0xffffffffu, Sh, o);
    }
    if ((t & 31) == 0) {
        int w5 = t >> 5;
        racc[0][w5] = S; racc[1][w5] = Sc; racc[2][w5] = Sr; racc[3][w5] = Sw; racc[4][w5] = Sh;
    }
    __syncthreads();
    if (t == 0) {
        float a0=0,a1=0,a2=0,a3=0,a4=0;
        #pragma unroll
        for (int k = 0; k < 8; ++k) { a0+=racc[0][k]; a1+=racc[1][k]; a2+=racc[2][k]; a3+=racc[3][k]; a4+=racc[4][k]; }
        float ws = a3 / a0, hs = a4 / a0;
        float x1 = a1 / a0 - ws * 0.5f;
        float y1 = a2 / a0 - hs * 0.5f;
        float* bb = out + (size_t)BB * 3 * CC * HW + (size_t)bc * 6;
        bb[0] = (float)b; bb[1] = x1; bb[2] = y1;
        bb[3] = x1 + ws;  bb[4] = y1 + hs; bb[5] = sps;
    }
}

// ---------------------------------------------------------------------------
// K2: all three branches in ONE launch (blockIdx.z dispatch) so their warps
// coexist and hide each other's latency. Disjoint output planes.
//   z=0: width  (horizontal conv; smem tile 8x144, no vertical halo)
//   z=1: height (vertical conv; column-per-thread sliding window, no smem tile)
//   z=2: score  (streaming argmax)
// grid (16, BB, 3), 256 threads.
// ---------------------------------------------------------------------------
#define WTP 144
#define WTILE (8 * WTP)     // 1152

__global__ __launch_bounds__(256) void k2_branches(
    const float* __restrict__ x,
    const float* __restrict__ w_bbx,
    const float* __restrict__ w_width,
    const float* __restrict__ w_width_sh,
    const float* __restrict__ w_height,
    const float* __restrict__ w_height_sh,
    float* __restrict__ out)
{
    __shared__ float pool[2 * WTILE + CC * 11 + CC];   // sized for width branch

    const int t = threadIdx.x;
    const int b = blockIdx.y;
    const int z = blockIdx.z;

    // ---------------- score branch ----------------
    if (z == 2) {
        float* sT = pool;
        if (t < CC) sT[t] = g_T[b * CC + t];
        __syncthreads();

        const int px = (blockIdx.x * 256 + t) << 2;
        const float* xp = x + (size_t)(b * CC) * HW + px;
        float mv[4] = {-INFINITY, -INFINITY, -INFINITY, -INFINITY};
        int   mi[4] = {0, 0, 0, 0};

        #pragma unroll 8
        for (int c = 0; c < CC; ++c) {
            float4 v = __ldg((const float4*)(xp + (size_t)c * HW));
            const float Tc = sT[c];
            float s0 = (v.x > Tc) ? v.x : 0.f;
            float s1 = (v.y > Tc) ? v.y : 0.f;
            float s2 = (v.z > Tc) ? v.z : 0.f;
            float s3 = (v.w > Tc) ? v.w : 0.f;
            if (s0 > mv[0]) { mv[0] = s0; mi[0] = c; }
            if (s1 > mv[1]) { mv[1] = s1; mi[1] = c; }
            if (s2 > mv[2]) { mv[2] = s2; mi[2] = c; }
            if (s3 > mv[3]) { mv[3] = s3; mi[3] = c; }
        }
        float* o = out + (size_t)(b * 3 * CC) * HW + px;
        #pragma unroll 8
        for (int c = 0; c < CC; ++c) {
            __stcs((float4*)(o + (size_t)c * HW),
                   make_float4(mi[0]==c ? mv[0] : 0.f, mi[1]==c ? mv[1] : 0.f,
                               mi[2]==c ? mv[2] : 0.f, mi[3]==c ? mv[3] : 0.f));
        }
        return;
    }

    // ---------------- height branch ----------------
    if (z == 1) {
        float* sch = pool;                 // CC*11
        float* ssH = pool + CC * 11;       // CC
        for (int i = t; i < CC * 11; i += 256) sch[i] = w_height[i];
        if (t < CC) ssH[t] = w_bbx[t] * 128.0f * w_height_sh[t];
        __syncthreads();

        const int col  = t & 127;
        const int row0 = (blockIdx.x * 2 + (t >> 7)) * 4;   // 0..124, 4 rows
        const float* xp0 = x + (size_t)(b * CC) * HW + col;

        float mH[4] = {-INFINITY, -INFINITY, -INFINITY, -INFINITY};
        int   iH[4] = {0, 0, 0, 0};

        for (int c = 0; c < CC; ++c) {
            const float* xp = xp0 + (size_t)c * HW;
            const float* ck = &sch[c * 11];
            float a0 = 0.f, a1 = 0.f, a2 = 0.f, a3 = 0.f;
            #pragma unroll
            for (int k = 0; k < 14; ++k) {
                int gr = row0 - 5 + k;
                float v = (gr >= 0 && gr < HH) ? __ldg(xp + (gr << 7)) : 0.f;
                if (k <= 10)           a0 = fmaf(v, ck[k],     a0);
                if (k >= 1 && k <= 11) a1 = fmaf(v, ck[k - 1], a1);
                if (k >= 2 && k <= 12) a2 = fmaf(v, ck[k - 2], a2);
                if (k >= 3)            a3 = fmaf(v, ck[k - 3], a3);
            }
            const float sHc = ssH[c];
            a0 *= sHc; a1 *= sHc; a2 *= sHc; a3 *= sHc;
            if (a0 > mH[0]) { mH[0] = a0; iH[0] = c; }
            if (a1 > mH[1]) { mH[1] = a1; iH[1] = c; }
            if (a2 > mH[2]) { mH[2] = a2; iH[2] = c; }
            if (a3 > mH[3]) { mH[3] = a3; iH[3] = c; }
        }
        float* o = out + ((size_t)(b * 3 * CC) + 2 * CC) * HW + ((size_t)row0 << 7) + col;
        for (int c = 0; c < CC; ++c) {
            #pragma unroll
            for (int j = 0; j < 4; ++j)
                __stcs(o + (size_t)c * HW + (j << 7), iH[j]==c ? mH[j] : 0.f);
        }
        return;
    }

    // ---------------- width branch ----------------
    {
        float* tile = pool;                       // 2 * WTILE
        float* scw  = pool + 2 * WTILE;           // CC*11
        float* ssW  = scw + CC * 11;              // CC

        const int row0 = blockIdx.x * 8;          // 8 rows, no vertical halo
        const int r    = t >> 5;                  // 0..7
        const int c4   = (t & 31) << 2;           // 0..124

        for (int i = t; i < WTILE; i += 256) {
            int col = i % WTP;
            if (col < 8 || col >= 136) { tile[i] = 0.f; tile[WTILE + i] = 0.f; }
        }
        for (int i = t; i < CC * 11; i += 256) scw[i] = w_width[i];
        if (t < CC) ssW[t] = w_bbx[t] * 128.0f * w_width_sh[t];

        const float* xp0 = x + (size_t)(b * CC) * HW + (row0 << 7);

        float regs[4];
        {
            #pragma unroll
            for (int j = 0; j < 4; ++j)
                regs[j] = __ldg(xp0 + t + j * 256);
            #pragma unroll
            for (int j = 0; j < 4; ++j) {
                int idx = t + j * 256;
                tile[(idx >> 7) * WTP + 8 + (idx & 127)] = regs[j];
            }
        }

        float mW[4] = {-INFINITY, -INFINITY, -INFINITY, -INFINITY};
        int   iW[4] = {0, 0, 0, 0};

        for (int c = 0; c < CC; ++c) {
            if (c + 1 < CC) {
                const float* xp = xp0 + (size_t)(c + 1) * HW;
                #pragma unroll
                for (int j = 0; j < 4; ++j)
                    regs[j] = __ldg(xp + t + j * 256);
            }
            __syncthreads();

            const float* tl = tile + (c & 1) * WTILE;
            float in[20];
            {
                const float* hrow = &tl[r * WTP + c4];   // data col c4-8
                #pragma unroll
                for (int m = 0; m < 5; ++m) {
                    float4 v = *(const float4*)(hrow + 4 * m);
                    in[4*m+0] = v.x; in[4*m+1] = v.y; in[4*m+2] = v.z; in[4*m+3] = v.w;
                }
            }
            float wv[4] = {0.f, 0.f, 0.f, 0.f};
            #pragma unroll
            for (int k = 0; k < 11; ++k) {
                float ck = scw[c * 11 + k];
                wv[0] = fmaf(in[3 + k], ck, wv[0]);
                wv[1] = fmaf(in[4 + k], ck, wv[1]);
                wv[2] = fmaf(in[5 + k], ck, wv[2]);
                wv[3] = fmaf(in[6 + k], ck, wv[3]);
            }
            const float sWc = ssW[c];
            #pragma unroll
            for (int j = 0; j < 4; ++j) {
                float w_ = wv[j] * sWc;
                if (w_ > mW[j]) { mW[j] = w_; iW[j] = c; }
            }

            if (c + 1 < CC) {
                float* tn = tile + ((c + 1) & 1) * WTILE;
                #pragma unroll
                for (int j = 0; j < 4; ++j) {
                    int idx = t + j * 256;
                    tn[(idx >> 7) * WTP + 8 + (idx & 127)] = regs[j];
                }
            }
        }

        float* o = out + ((size_t)(b * 3 * CC) + CC) * HW + ((size_t)(row0 + r) << 7) + c4;
        #pragma unroll 8
        for (int c = 0; c < CC; ++c) {
            __stcs((float4*)(o + (size_t)c * HW),
                   make_float4(iW[0]==c ? mW[0] : 0.f, iW[1]==c ? mW[1] : 0.f,
                               iW[2]==c ? mW[2] : 0.f, iW[3]==c ? mW[3] : 0.f));
        }
    }
}

extern "C" void kernel_launch(void* const* d_in, const int* in_sizes, int n_in,
                              void* d_out, int out_size)
{
    const float* x           = (const float*)d_in[0];
    const float* w_bbx       = (const float*)d_in[1];
    const float* w_width     = (const float*)d_in[2];
    const float* w_width_sh  = (const float*)d_in[3];
    const float* w_height    = (const float*)d_in[4];
    const float* w_height_sh = (const float*)d_in[5];
    float* out = (float*)d_out;

    k1_stats<<<BC, 256>>>(x, w_bbx, w_width, w_width_sh, w_height, w_height_sh, out);

    dim3 g2(16, BB, 3);
    k2_branches<<<g2, 256>>>(x, w_bbx, w_width, w_width_sh, w_height, w_height_sh, out);
}

// round 9
// speedup vs baseline: 2.0590x; 1.2226x over previous
#include <cuda_runtime.h>
#include <math.h>

#define BB  16
#define CC  64
#define HH  128
#define WW  128
#define HW  (HH*WW)
#define BC  (BB*CC)

// Per-(b,c) x-space threshold T = logit(sigmoid(max x) - 0.01), from k1.
__device__ float g_T[BC];

__device__ __forceinline__ float sigmoidf_(float v) {
    return 1.0f / (1.0f + expf(-v));
}

// ---------------------------------------------------------------------------
// K1: per-(b,c) plane. max(x) -> ps, threshold T; masked sums -> bbox row.
// (unchanged — passing since round 3)
// ---------------------------------------------------------------------------
__global__ __launch_bounds__(256) void k1_stats(
    const float* __restrict__ x,
    const float* __restrict__ w_bbx,
    const float* __restrict__ w_width,
    const float* __restrict__ w_width_sh,
    const float* __restrict__ w_height,
    const float* __restrict__ w_height_sh,
    float* __restrict__ out)
{
    const int bc = blockIdx.x;
    const int b  = bc / CC;
    const int c  = bc % CC;
    const float* __restrict__ xp = x + (size_t)bc * HW;
    const int t = threadIdx.x;

    float mx = -INFINITY;
    #pragma unroll
    for (int j = 0; j < 16; ++j) {
        float4 v = *(const float4*)(xp + 1024 * j + 4 * t);
        mx = fmaxf(fmaxf(fmaxf(mx, v.x), fmaxf(v.y, v.z)), v.w);
    }
    __shared__ float red[8];
    #pragma unroll
    for (int o = 16; o; o >>= 1) mx = fmaxf(mx, __shfl_xor_sync(0xffffffffu, mx, o));
    if ((t & 31) == 0) red[t >> 5] = mx;
    __syncthreads();
    __shared__ float sT, sps;
    if (t == 0) {
        float v = red[0];
        #pragma unroll
        for (int k = 1; k < 8; ++k) v = fmaxf(v, red[k]);
        float ps = sigmoidf_(v);
        float M  = ps - 0.01f;
        float T;
        if (M > 0.0f) {
            double dM = (double)M;
            T = (float)log(dM / (1.0 - dM));
        } else {
            T = -INFINITY;
        }
        sT = T; sps = ps;
        g_T[bc] = T;
    }
    __syncthreads();
    const float T = sT;

    float cw[11], ch[11];
    #pragma unroll
    for (int k = 0; k < 11; ++k) { cw[k] = w_width[c*11+k]; ch[k] = w_height[c*11+k]; }
    const float s0 = w_bbx[c] * 128.0f;
    const float sW = s0 * w_width_sh[c];
    const float sH = s0 * w_height_sh[c];

    float S = 0.f, Sc = 0.f, Sr = 0.f, Sw = 0.f, Sh = 0.f;
    #pragma unroll
    for (int j = 0; j < 16; ++j) {
        const int i0 = 1024 * j + 4 * t;
        float4 v4 = *(const float4*)(xp + i0);
        float vv[4] = {v4.x, v4.y, v4.z, v4.w};
        if (vv[0] > T || vv[1] > T || vv[2] > T || vv[3] > T) {
            #pragma unroll
            for (int u = 0; u < 4; ++u) {
                float v = vv[u];
                if (v > T) {
                    int i = i0 + u;
                    int row = i >> 7, col = i & 127;
                    S  += v;
                    Sc += (float)col * v;
                    Sr += (float)row * v;
                    float wvv = 0.f;
                    #pragma unroll
                    for (int k = 0; k < 11; ++k) {
                        int cc2 = col - 5 + k;
                        if (cc2 >= 0 && cc2 < WW) wvv = fmaf(xp[(row << 7) + cc2], cw[k], wvv);
                    }
                    float hvv = 0.f;
                    #pragma unroll
                    for (int k = 0; k < 11; ++k) {
                        int rr = row - 5 + k;
                        if (rr >= 0 && rr < HH) hvv = fmaf(xp[(rr << 7) + col], ch[k], hvv);
                    }
                    Sw += wvv * sW * v;
                    Sh += hvv * sH * v;
                }
            }
        }
    }
    __shared__ float racc[5][8];
    #pragma unroll
    for (int o = 16; o; o >>= 1) {
        S  += __shfl_xor_sync(0xffffffffu, S,  o);
        Sc += __shfl_xor_sync(0xffffffffu, Sc, o);
        Sr += __shfl_xor_sync(0xffffffffu, Sr, o);
        Sw += __shfl_xor_sync(0xffffffffu, Sw, o);
        Sh += __shfl_xor_sync(0xffffffffu, Sh, o);
    }
    if ((t & 31) == 0) {
        int w5 = t >> 5;
        racc[0][w5] = S; racc[1][w5] = Sc; racc[2][w5] = Sr; racc[3][w5] = Sw; racc[4][w5] = Sh;
    }
    __syncthreads();
    if (t == 0) {
        float a0=0,a1=0,a2=0,a3=0,a4=0;
        #pragma unroll
        for (int k = 0; k < 8; ++k) { a0+=racc[0][k]; a1+=racc[1][k]; a2+=racc[2][k]; a3+=racc[3][k]; a4+=racc[4][k]; }
        float ws = a3 / a0, hs = a4 / a0;
        float x1 = a1 / a0 - ws * 0.5f;
        float y1 = a2 / a0 - hs * 0.5f;
        float* bb = out + (size_t)BB * 3 * CC * HW + (size_t)bc * 6;
        bb[0] = (float)b; bb[1] = x1; bb[2] = y1;
        bb[3] = x1 + ws;  bb[4] = y1 + hs; bb[5] = sps;
    }
}

// ---------------------------------------------------------------------------
// K2 fused (round-5 structure) + channel-PAIR unroll (2 independent LDS->FMA
// chains per thread, 1 barrier per 2 channels) + ALU-free epilogue
// (unconditional zero-blast then 12 scattered stores).
// 256 threads: r = t>>5 (8 rows), c4 = (t&31)<<2 (4 cols, 16B-aligned).
// ---------------------------------------------------------------------------
#define RG 8
#define TR 18
#define TP 144
#define NFILL 9
#define TILE_SZ (TR * TP)

__global__ __launch_bounds__(256) void k2_fused(
    const float* __restrict__ x,
    const float* __restrict__ w_bbx,
    const float* __restrict__ w_width,
    const float* __restrict__ w_width_sh,
    const float* __restrict__ w_height,
    const float* __restrict__ w_height_sh,
    float* __restrict__ out)
{
    __shared__ float tile[4][TILE_SZ];   // ring of 4 (2 pairs)
    __shared__ float scw[CC * 11], sch[CC * 11];
    __shared__ float ssW[CC], ssH[CC], sTv[CC];

    const int t    = threadIdx.x;
    const int b    = blockIdx.y;
    const int rg   = blockIdx.x;          // 0..15
    const int row0 = rg * RG;
    const int r    = t >> 5;              // 0..7
    const int c4   = (t & 31) << 2;       // 0..124
    const int grow = row0 + r;

    // zero pads once for all 4 buffers (fills never touch them)
    for (int i = t; i < TILE_SZ; i += 256) {
        int col = i % TP;
        if (col < 8 || col >= 136) {
            tile[0][i] = 0.f; tile[1][i] = 0.f; tile[2][i] = 0.f; tile[3][i] = 0.f;
        }
    }
    for (int i = t; i < CC * 11; i += 256) { scw[i] = w_width[i]; sch[i] = w_height[i]; }
    if (t < CC) {
        float s0 = w_bbx[t] * 128.0f;
        ssW[t] = s0 * w_width_sh[t];
        ssH[t] = s0 * w_height_sh[t];
        sTv[t] = g_T[b * CC + t];
    }

    // fill staging geometry
    int   fidx[NFILL];
    bool  fok[NFILL];
    #pragma unroll
    for (int j = 0; j < NFILL; ++j) {
        int idx = t + j * 256;
        fidx[j] = (idx >> 7) * TP + 8 + (idx & 127);
        int gr  = row0 - 5 + (idx >> 7);
        fok[j]  = (gr >= 0 && gr < HH);
    }
    int goff[NFILL];
    #pragma unroll
    for (int j = 0; j < NFILL; ++j) {
        int idx = t + j * 256;
        goff[j] = ((row0 - 5 + (idx >> 7)) << 7) + (idx & 127);
    }

    float regs[2][NFILL];
    const float* xp0 = x + (size_t)(b * CC) * HW;

    // prologue: stage + store pair 0 (channels 0,1)
    #pragma unroll
    for (int p = 0; p < 2; ++p) {
        const float* xp = xp0 + (size_t)p * HW;
        #pragma unroll
        for (int j = 0; j < NFILL; ++j)
            regs[p][j] = fok[j] ? __ldg(xp + goff[j]) : 0.f;
        #pragma unroll
        for (int j = 0; j < NFILL; ++j)
            tile[p][fidx[j]] = regs[p][j];
    }

    float mS[4], mW[4], mH[4];
    int   iS[4], iW[4], iH[4];
    #pragma unroll
    for (int j = 0; j < 4; ++j) {
        mS[j] = -INFINITY; mW[j] = -INFINITY; mH[j] = -INFINITY;
        iS[j] = 0; iW[j] = 0; iH[j] = 0;
    }

    for (int cp = 0; cp < CC / 2; ++cp) {
        const int cur = (cp & 1) << 1;          // 0 or 2
        const int c0 = 2 * cp, c1 = 2 * cp + 1;

        // stage next pair (LDGs overlap barrier + compute)
        if (cp + 1 < CC / 2) {
            #pragma unroll
            for (int p = 0; p < 2; ++p) {
                const float* xp = xp0 + (size_t)(2 * cp + 2 + p) * HW;
                #pragma unroll
                for (int j = 0; j < NFILL; ++j)
                    regs[p][j] = fok[j] ? __ldg(xp + goff[j]) : 0.f;
            }
        }
        __syncthreads();   // tile[cur], tile[cur+1] ready; other pair consumed

        const float* tl0 = tile[cur];
        const float* tl1 = tile[cur + 1];

        // horizontal windows for both channels (independent chains)
        float in0[20], in1[20];
        {
            const float* h0 = &tl0[(r + 5) * TP + c4];
            const float* h1 = &tl1[(r + 5) * TP + c4];
            #pragma unroll
            for (int m = 0; m < 5; ++m) {
                float4 v0 = *(const float4*)(h0 + 4 * m);
                float4 v1 = *(const float4*)(h1 + 4 * m);
                in0[4*m+0] = v0.x; in0[4*m+1] = v0.y; in0[4*m+2] = v0.z; in0[4*m+3] = v0.w;
                in1[4*m+0] = v1.x; in1[4*m+1] = v1.y; in1[4*m+2] = v1.z; in1[4*m+3] = v1.w;
            }
        }
        // vertical convs (interleaved)
        float hv0[4] = {0.f,0.f,0.f,0.f}, hv1[4] = {0.f,0.f,0.f,0.f};
        #pragma unroll
        for (int k = 0; k < 11; ++k) {
            float4 v0 = *(const float4*)(&tl0[(r + k) * TP + 8 + c4]);
            float4 v1 = *(const float4*)(&tl1[(r + k) * TP + 8 + c4]);
            float ck0 = sch[c0 * 11 + k];
            float ck1 = sch[c1 * 11 + k];
            hv0[0] = fmaf(v0.x, ck0, hv0[0]);  hv1[0] = fmaf(v1.x, ck1, hv1[0]);
            hv0[1] = fmaf(v0.y, ck0, hv0[1]);  hv1[1] = fmaf(v1.y, ck1, hv1[1]);
            hv0[2] = fmaf(v0.z, ck0, hv0[2]);  hv1[2] = fmaf(v1.z, ck1, hv1[2]);
            hv0[3] = fmaf(v0.w, ck0, hv0[3]);  hv1[3] = fmaf(v1.w, ck1, hv1[3]);
        }
        // horizontal convs (interleaved)
        float wv0[4] = {0.f,0.f,0.f,0.f}, wv1[4] = {0.f,0.f,0.f,0.f};
        #pragma unroll
        for (int k = 0; k < 11; ++k) {
            float ck0 = scw[c0 * 11 + k];
            float ck1 = scw[c1 * 11 + k];
            wv0[0] = fmaf(in0[3 + k], ck0, wv0[0]);  wv1[0] = fmaf(in1[3 + k], ck1, wv1[0]);
            wv0[1] = fmaf(in0[4 + k], ck0, wv0[1]);  wv1[1] = fmaf(in1[4 + k], ck1, wv1[1]);
            wv0[2] = fmaf(in0[5 + k], ck0, wv0[2]);  wv1[2] = fmaf(in1[5 + k], ck1, wv1[2]);
            wv0[3] = fmaf(in0[6 + k], ck0, wv0[3]);  wv1[3] = fmaf(in1[6 + k], ck1, wv1[3]);
        }
        {
            const float sW0 = ssW[c0], sH0 = ssH[c0], T0 = sTv[c0];
            const float sW1 = ssW[c1], sH1 = ssH[c1], T1 = sTv[c1];
            #pragma unroll
            for (int j = 0; j < 4; ++j) {
                float w0 = wv0[j] * sW0, w1 = wv1[j] * sW1;
                float h0 = hv0[j] * sH0, h1 = hv1[j] * sH1;
                float x0 = in0[8 + j],   x1 = in1[8 + j];
                float s0 = (x0 > T0) ? x0 : 0.f;
                float s1 = (x1 > T1) ? x1 : 0.f;
                if (s0 > mS[j]) { mS[j] = s0; iS[j] = c0; }
                if (w0 > mW[j]) { mW[j] = w0; iW[j] = c0; }
                if (h0 > mH[j]) { mH[j] = h0; iH[j] = c0; }
                if (s1 > mS[j]) { mS[j] = s1; iS[j] = c1; }
                if (w1 > mW[j]) { mW[j] = w1; iW[j] = c1; }
                if (h1 > mH[j]) { mH[j] = h1; iH[j] = c1; }
            }
        }

        if (cp + 1 < CC / 2) {
            const int nxt = ((cp + 1) & 1) << 1;
            #pragma unroll
            for (int p = 0; p < 2; ++p) {
                float* tn = tile[nxt + p];
                #pragma unroll
                for (int j = 0; j < NFILL; ++j)
                    tn[fidx[j]] = regs[p][j];
            }
        }
    }

    // ------------- epilogue: zero-blast then scatter (no per-channel ALU) ----
    const size_t ob = (size_t)(b * 3 * CC) * HW + ((size_t)grow << 7) + c4;
    float* oS = out + ob;
    float* oW = oS + (size_t)CC * HW;
    float* oH = oS + (size_t)2 * CC * HW;
    const float4 z4 = make_float4(0.f, 0.f, 0.f, 0.f);
    #pragma unroll 4
    for (int c = 0; c < CC; ++c) {
        const size_t off = (size_t)c * HW;
        __stcs((float4*)(oS + off), z4);
        __stcs((float4*)(oW + off), z4);
        __stcs((float4*)(oH + off), z4);
    }
    // scattered one-hot writes (same thread wrote the zeros above -> ordered)
    #pragma unroll
    for (int j = 0; j < 4; ++j) {
        oS[(size_t)iS[j] * HW + j] = mS[j];
        oW[(size_t)iW[j] * HW + j] = mW[j];
        oH[(size_t)iH[j] * HW + j] = mH[j];
    }
}

extern "C" void kernel_launch(void* const* d_in, const int* in_sizes, int n_in,
                              void* d_out, int out_size)
{
    const float* x           = (const float*)d_in[0];
    const float* w_bbx       = (const float*)d_in[1];
    const float* w_width     = (const float*)d_in[2];
    const float* w_width_sh  = (const float*)d_in[3];
    const float* w_height    = (const float*)d_in[4];
    const float* w_height_sh = (const float*)d_in[5];
    float* out = (float*)d_out;

    k1_stats<<<BC, 256>>>(x, w_bbx, w_width, w_width_sh, w_height, w_height_sh, out);

    dim3 g2(16, BB);
    k2_fused<<<g2, 256>>>(x, w_bbx, w_width, w_width_sh, w_height, w_height_sh, out);
}